// round 16
// baseline (speedup 1.0000x reference)
#include <cuda_runtime.h>
#include <cuda_bf16.h>
#include <cstddef>

// Problem constants
#define N_ 400000
#define E_ 1600000
#define B_ 8192
#define F_ 64
#define H_ 96
#define N2_ 800000                      // combined nodes (2 sides)
#define E2_ 3200000                     // combined edges
#define NT2_ ((N2_ + 1023) / 1024)      // 782 scan tiles

// ---------------- scratch (device globals; no allocations allowed) ----------------
__device__ __nv_bfloat16 g_xh [(size_t)N2_ * F_];   // dinv-prescaled bf16 x
__device__ __nv_bfloat16 g_bufA[(size_t)N2_ * H_];  // dinv-prescaled layer1 out
__device__ __nv_bfloat16 g_bufB[(size_t)N2_ * H_];  // dinv-prescaled layer2 out
__device__ float g_dinv[N2_];
__device__ int   g_deg[N2_];
__device__ int   g_rowptr[N2_ + 1];
__device__ int   g_fill[N2_];
__device__ int   g_csr[E2_];
__device__ int   g_bsum[NT2_];
__device__ float g_gate[N2_];
__device__ int   g_boffs[2][B_ + 1];
__device__ float g_att [2][B_ * F_];
__device__ float g_mean[2][B_ * H_];

// HMMA bf16: D(16x8,f32) += A(16x16,bf16 row) * B(16x8,bf16 col)
__device__ __forceinline__ void mma_bf16(float& c0, float& c1, float& c2, float& c3,
                                         unsigned a0, unsigned a1, unsigned a2, unsigned a3,
                                         unsigned b0, unsigned b1) {
    asm volatile(
        "mma.sync.aligned.m16n8k16.row.col.f32.bf16.bf16.f32 "
        "{%0,%1,%2,%3}, {%4,%5,%6,%7}, {%8,%9}, {%0,%1,%2,%3};"
        : "+f"(c0), "+f"(c1), "+f"(c2), "+f"(c3)
        : "r"(a0), "r"(a1), "r"(a2), "r"(a3), "r"(b0), "r"(b1));
}

// HMMA tf32: D(16x8,f32) += A(16x8,tf32 row) * B(8x8,tf32 col)
__device__ __forceinline__ void mma_tf32(float& c0, float& c1, float& c2, float& c3,
                                         unsigned a0, unsigned a1, unsigned a2, unsigned a3,
                                         unsigned b0, unsigned b1) {
    asm volatile(
        "mma.sync.aligned.m16n8k8.row.col.f32.tf32.tf32.f32 "
        "{%0,%1,%2,%3}, {%4,%5,%6,%7}, {%8,%9}, {%0,%1,%2,%3};"
        : "+f"(c0), "+f"(c1), "+f"(c2), "+f"(c3)
        : "r"(a0), "r"(a1), "r"(a2), "r"(a3), "r"(b0), "r"(b1));
}

__device__ __forceinline__ unsigned f2tf32(float f) {
    unsigned u;
    asm("cvt.rna.tf32.f32 %0, %1;" : "=r"(u) : "f"(f));
    return u;
}

// ---------------- gate MLP (both sides, tf32 HMMA) + prescaled bf16 x emission ----------------
__global__ void k_gate(const float* __restrict__ x_p, const float* __restrict__ x_d,
                       const float* __restrict__ W1, const float* __restrict__ b1,
                       const float* __restrict__ W2, const float* __restrict__ b2) {
    extern __shared__ char sm_raw[];
    float* xs  = (float*)sm_raw;                       // [64][68] row-major
    float* W1T = xs + 64 * 68;                          // [64n][68k]
    float* b1s = W1T + 64 * 68;
    float* W2s = b1s + 64;
    __shared__ float gred[64][2];
    int tid = threadIdx.x;
    int side = blockIdx.x >= (N_ / 64);
    int lrow0 = (blockIdx.x - side * (N_ / 64)) * 64;
    const float* x = side ? x_d : x_p;
    size_t gbase = (size_t)side * N_;

    for (int i = tid; i < 64 * 64; i += 256) {
        int k = i >> 6, n = i & 63;
        W1T[n * 68 + k] = W1[i];
    }
    if (tid < 64) { b1s[tid] = b1[tid]; W2s[tid] = W2[tid]; }

    // stage x rows (unscaled, for GEMM) + emit dinv-prescaled bf16 copy
    {
        int g = tid >> 2, l = tid & 3;
        float dn = g_dinv[gbase + lrow0 + g];
        const float4* sp = (const float4*)(x + (size_t)(lrow0 + g) * 64) + l * 4;
        __nv_bfloat162 hv[8];
#pragma unroll
        for (int j = 0; j < 4; ++j) {
            float4 v = sp[j];
            *(float4*)&xs[g * 68 + l * 16 + j * 4] = v;
            hv[2 * j]     = __float22bfloat162_rn(make_float2(v.x * dn, v.y * dn));
            hv[2 * j + 1] = __float22bfloat162_rn(make_float2(v.z * dn, v.w * dn));
        }
        *(uint4*)(g_xh + (gbase + lrow0 + g) * 64 + l * 16)     = *(uint4*)&hv[0];
        *(uint4*)(g_xh + (gbase + lrow0 + g) * 64 + l * 16 + 8) = *(uint4*)&hv[4];
    }
    __syncthreads();

    int lane = tid & 31, w = tid >> 5;
    int g = lane >> 2, tig = lane & 3;
    int rw = (w >> 1) * 16, cw = (w & 1) * 32;
    float hacc[4][4];
#pragma unroll
    for (int nt = 0; nt < 4; ++nt)
#pragma unroll
        for (int q = 0; q < 4; ++q) hacc[nt][q] = 0.f;

#pragma unroll
    for (int k0 = 0; k0 < 64; k0 += 8) {
        unsigned a0 = f2tf32(xs[(rw + g) * 68 + k0 + tig]);
        unsigned a1 = f2tf32(xs[(rw + g + 8) * 68 + k0 + tig]);
        unsigned a2 = f2tf32(xs[(rw + g) * 68 + k0 + tig + 4]);
        unsigned a3 = f2tf32(xs[(rw + g + 8) * 68 + k0 + tig + 4]);
#pragma unroll
        for (int nt = 0; nt < 4; ++nt) {
            int n = cw + nt * 8 + g;
            unsigned b0 = f2tf32(W1T[n * 68 + k0 + tig]);
            unsigned b1r = f2tf32(W1T[n * 68 + k0 + tig + 4]);
            mma_tf32(hacc[nt][0], hacc[nt][1], hacc[nt][2], hacc[nt][3],
                     a0, a1, a2, a3, b0, b1r);
        }
    }

    float p0 = 0.f, p1 = 0.f;
#pragma unroll
    for (int nt = 0; nt < 4; ++nt) {
        int col = cw + nt * 8 + tig * 2;
        float ba = b1s[col], bb = b1s[col + 1];
        float wa = W2s[col], wb = W2s[col + 1];
        p0 += fmaxf(hacc[nt][0] + ba, 0.f) * wa + fmaxf(hacc[nt][1] + bb, 0.f) * wb;
        p1 += fmaxf(hacc[nt][2] + ba, 0.f) * wa + fmaxf(hacc[nt][3] + bb, 0.f) * wb;
    }
    p0 += __shfl_xor_sync(0xffffffffu, p0, 1);
    p0 += __shfl_xor_sync(0xffffffffu, p0, 2);
    p1 += __shfl_xor_sync(0xffffffffu, p1, 1);
    p1 += __shfl_xor_sync(0xffffffffu, p1, 2);
    if (tig == 0) {
        gred[rw + g][w & 1] = p0;
        gred[rw + g + 8][w & 1] = p1;
    }
    __syncthreads();
    if (tid < 64)
        g_gate[gbase + lrow0 + tid] = gred[tid][0] + gred[tid][1] + b2[0];
}

// ---------------- batch segment offsets ----------------
__global__ void k_boffs(const int* __restrict__ bat_p, const int* __restrict__ bat_d) {
    int gi = blockIdx.x * blockDim.x + threadIdx.x;
    if (gi >= N2_) return;
    int side = gi >= N_;
    int i = gi - side * N_;
    const int* batch = side ? bat_d : bat_p;
    int b = batch[i];
    if (i == 0) {
        for (int bb = 0; bb <= b; ++bb) g_boffs[side][bb] = 0;
    } else {
        int pb = batch[i - 1];
        for (int bb = pb + 1; bb <= b; ++bb) g_boffs[side][bb] = i;
    }
    if (i == N_ - 1) {
        for (int bb = b + 1; bb <= B_; ++bb) g_boffs[side][bb] = N_;
    }
}

// ---------------- attention pool ----------------
__global__ void k_att(const float* __restrict__ x_p, const float* __restrict__ x_d) {
    __shared__ float sred[256];
    __shared__ float red[64][64];
    int side = blockIdx.x >> 13;
    int b = blockIdx.x & (B_ - 1);
    int tid = threadIdx.x;
    const float* x = side ? x_d : x_p;
    const float* gate = g_gate + (size_t)side * N_;
    int start = g_boffs[side][b], end = g_boffs[side][b + 1];

    float m = -1e30f;
    for (int i = start + tid; i < end; i += 256) m = fmaxf(m, gate[i]);
    sred[tid] = m;
    __syncthreads();
    for (int o = 128; o > 0; o >>= 1) {
        if (tid < o) sred[tid] = fmaxf(sred[tid], sred[tid + o]);
        __syncthreads();
    }
    float gmax = sred[0];
    __syncthreads();

    float s = 0.f;
    for (int i = start + tid; i < end; i += 256) s += expf(gate[i] - gmax);
    sred[tid] = s;
    __syncthreads();
    for (int o = 128; o > 0; o >>= 1) {
        if (tid < o) sred[tid] += sred[tid + o];
        __syncthreads();
    }
    float denom = sred[0];

    int slot = tid >> 2, l = tid & 3;
    float4 acc[4];
#pragma unroll
    for (int j = 0; j < 4; ++j) acc[j] = make_float4(0.f, 0.f, 0.f, 0.f);
    for (int i = start + slot; i < end; i += 64) {
        float e = expf(gate[i] - gmax);
        const float4* xp = (const float4*)(x + (size_t)i * 64) + l * 4;
#pragma unroll
        for (int j = 0; j < 4; ++j) {
            float4 v = xp[j];
            acc[j].x += e * v.x; acc[j].y += e * v.y;
            acc[j].z += e * v.z; acc[j].w += e * v.w;
        }
    }
#pragma unroll
    for (int j = 0; j < 4; ++j) *(float4*)&red[slot][l * 16 + j * 4] = acc[j];
    __syncthreads();
    for (int o = 32; o > 0; o >>= 1) {
        if (slot < o) {
#pragma unroll
            for (int j = 0; j < 4; ++j) {
                float4 a = *(float4*)&red[slot][l * 16 + j * 4];
                float4 c = *(float4*)&red[slot + o][l * 16 + j * 4];
                a.x += c.x; a.y += c.y; a.z += c.z; a.w += c.w;
                *(float4*)&red[slot][l * 16 + j * 4] = a;
            }
        }
        __syncthreads();
    }
    if (slot == 0) {
        float inv = (end > start) ? 1.f / denom : 0.f;
#pragma unroll
        for (int j = 0; j < 16; ++j)
            g_att[side][(size_t)b * 64 + l * 16 + j] = red[0][l * 16 + j] * inv;
    }
}

// ---------------- combined CSR build ----------------
__global__ void k_csr_init() {
    int i = blockIdx.x * blockDim.x + threadIdx.x;
    if (i < N2_) { g_deg[i] = 0; g_fill[i] = 0; }
}
__global__ void k_count(const int* __restrict__ ei_p, const int* __restrict__ ei_d) {
    int e = blockIdx.x * blockDim.x + threadIdx.x;
    if (e >= E2_) return;
    int side = e >= E_;
    int idx = e - side * E_;
    const int* ei = side ? ei_d : ei_p;
    atomicAdd(&g_deg[ei[E_ + idx] + side * N_], 1);
}
__global__ void k_scan1() {
    __shared__ int s[1024];
    int tx = threadIdx.x;
    int i = blockIdx.x * 1024 + tx;
    int v = (i < N2_) ? g_deg[i] : 0;
    s[tx] = v;
    __syncthreads();
    for (int o = 1; o < 1024; o <<= 1) {
        int t = (tx >= o) ? s[tx - o] : 0;
        __syncthreads();
        s[tx] += t;
        __syncthreads();
    }
    if (i < N2_) g_rowptr[i] = s[tx] - v;
    if (tx == 1023) g_bsum[blockIdx.x] = s[1023];
}
__global__ void k_scan2() {
    __shared__ int s[1024];
    int tx = threadIdx.x;
    int v = (tx < NT2_) ? g_bsum[tx] : 0;
    s[tx] = v;
    __syncthreads();
    for (int o = 1; o < 1024; o <<= 1) {
        int t = (tx >= o) ? s[tx - o] : 0;
        __syncthreads();
        s[tx] += t;
        __syncthreads();
    }
    if (tx < NT2_) g_bsum[tx] = s[tx] - v;
}
__global__ void k_scan3() {     // + fused dinv
    int i = blockIdx.x * blockDim.x + threadIdx.x;
    if (i < N2_) {
        g_rowptr[i] += g_bsum[i >> 10];
        g_dinv[i] = rsqrtf((float)(g_deg[i] + 1));
    }
    if (i == 0) g_rowptr[N2_] = E2_;
}
__global__ void k_fill(const int* __restrict__ ei_p, const int* __restrict__ ei_d) {
    int e = blockIdx.x * blockDim.x + threadIdx.x;
    if (e >= E2_) return;
    int side = e >= E_;
    int idx = e - side * E_;
    const int* ei = side ? ei_d : ei_p;
    int d = ei[E_ + idx] + side * N_;
    int pos = g_rowptr[d] + atomicAdd(&g_fill[d], 1);
    g_csr[pos] = ei[idx] + side * N_;
}

// ---------------- fused layer (HMMA): out' = dinv * relu(agg(in') @ W + b) ----------------
// in'/out' are dinv-prescaled. agg_d = dinv_d * (in'_d + sum_nbr in'_s).
// block = 64 dst rows, 256 threads. Quad-shuffle index loading (QUAD-masked — cross-quad
// divergence is fine), 4-neighbor unroll.
template <int FIN>
__global__ void __launch_bounds__(256, 2) k_layer(
        const __nv_bfloat16* __restrict__ in, const float* __restrict__ W,
        const float* __restrict__ bias, __nv_bfloat16* __restrict__ out, int side) {
    constexpr int AP = FIN + 8;
    constexpr int CH = FIN / 4;          // features per lane
    constexpr int NV = CH / 8;           // uint4 per lane per row (2 or 3)
    extern __shared__ char sm_raw[];
    __nv_bfloat16* As = (__nv_bfloat16*)sm_raw;
    __nv_bfloat16* Wt = As + 64 * AP;
    float* bs = (float*)(sm_raw + (64 + 96) * AP * 2);
    int tid = threadIdx.x;
    size_t row0 = (size_t)side * N_ + blockIdx.x * 64;

    for (int i = tid; i < FIN * 96; i += 256) {
        int k = i / 96, n = i % 96;
        Wt[n * AP + k] = __float2bfloat16(W[i]);
    }
    if (tid < 96) bs[tid] = bias[tid];

    // ---- gather phase ----
    {
        int g = tid >> 2, l = tid & 3;
        int lane = tid & 31;
        int qb = lane & ~3;                       // quad base lane
        unsigned QM = 0xFu << qb;                 // quad member mask
        size_t node = row0 + g;
        float dn = g_dinv[node];

        int r = 0;
        if (l < 2) r = g_rowptr[node + l];
        int pstart = __shfl_sync(QM, r, qb);
        int pend   = __shfl_sync(QM, r, qb + 1);

        float2 acc[CH / 2];
        const uint4* sp = (const uint4*)(in + node * FIN + l * CH);
#pragma unroll
        for (int v = 0; v < NV; ++v) {
            uint4 u = sp[v];
            const __nv_bfloat162* h = (const __nv_bfloat162*)&u;
#pragma unroll
            for (int q = 0; q < 4; ++q)
                acc[v * 4 + q] = __bfloat1622float2(h[q]);
        }
        for (int p = pstart; p < pend; p += 4) {
            int myi = p + l;
            int sl = (myi < pend) ? g_csr[myi] : -1;
            const uint4* bp[4];
            float wg[4];
#pragma unroll
            for (int j = 0; j < 4; ++j) {
                int sj = __shfl_sync(QM, sl, qb + j);
                int sjc = sj >= 0 ? sj : 0;
                bp[j] = (const uint4*)(in + (size_t)sjc * FIN + l * CH);
                wg[j] = sj >= 0 ? 1.f : 0.f;
            }
            uint4 u[4][NV];
#pragma unroll
            for (int j = 0; j < 4; ++j)
#pragma unroll
                for (int v = 0; v < NV; ++v) u[j][v] = bp[j][v];
#pragma unroll
            for (int j = 0; j < 4; ++j) {
#pragma unroll
                for (int v = 0; v < NV; ++v) {
                    const __nv_bfloat162* h = (const __nv_bfloat162*)&u[j][v];
#pragma unroll
                    for (int q = 0; q < 4; ++q) {
                        float2 vv = __bfloat1622float2(h[q]);
                        acc[v * 4 + q].x += wg[j] * vv.x;
                        acc[v * 4 + q].y += wg[j] * vv.y;
                    }
                }
            }
        }
#pragma unroll
        for (int j2 = 0; j2 < CH / 2; ++j2) {
            float2 a = acc[j2];
            a.x *= dn; a.y *= dn;
            *(__nv_bfloat162*)(As + g * AP + l * CH + 2 * j2) = __float22bfloat162_rn(a);
        }
    }
    __syncthreads();

    // ---- HMMA phase: [64 x FIN] @ [FIN x 96] ----
    int lane = tid & 31, w = tid >> 5;
    int g = lane >> 2, tig = lane & 3;
    int rw = (w >> 1) * 16, cw = (w & 1) * 48;
    float acc[6][4];
#pragma unroll
    for (int nt = 0; nt < 6; ++nt)
#pragma unroll
        for (int q = 0; q < 4; ++q) acc[nt][q] = 0.f;

#pragma unroll
    for (int k0 = 0; k0 < FIN; k0 += 16) {
        unsigned a0 = *(const unsigned*)(As + (rw + g) * AP + k0 + 2 * tig);
        unsigned a1 = *(const unsigned*)(As + (rw + g + 8) * AP + k0 + 2 * tig);
        unsigned a2 = *(const unsigned*)(As + (rw + g) * AP + k0 + 2 * tig + 8);
        unsigned a3 = *(const unsigned*)(As + (rw + g + 8) * AP + k0 + 2 * tig + 8);
#pragma unroll
        for (int nt = 0; nt < 6; ++nt) {
            int n = cw + nt * 8 + g;
            unsigned b0 = *(const unsigned*)(Wt + n * AP + k0 + 2 * tig);
            unsigned b1 = *(const unsigned*)(Wt + n * AP + k0 + 2 * tig + 8);
            mma_bf16(acc[nt][0], acc[nt][1], acc[nt][2], acc[nt][3],
                     a0, a1, a2, a3, b0, b1);
        }
    }

    // ---- epilogue: bias + relu + prescale by dinv(out row) + bf16 store ----
    float d0 = g_dinv[row0 + rw + g];
    float d1 = g_dinv[row0 + rw + g + 8];
#pragma unroll
    for (int nt = 0; nt < 6; ++nt) {
        int col = cw + nt * 8 + tig * 2;
        float bx = bs[col], by = bs[col + 1];
        float2 v0 = make_float2(fmaxf(acc[nt][0] + bx, 0.f) * d0,
                                fmaxf(acc[nt][1] + by, 0.f) * d0);
        float2 v1 = make_float2(fmaxf(acc[nt][2] + bx, 0.f) * d1,
                                fmaxf(acc[nt][3] + by, 0.f) * d1);
        *(__nv_bfloat162*)(out + (row0 + rw + g) * 96 + col)     = __float22bfloat162_rn(v0);
        *(__nv_bfloat162*)(out + (row0 + rw + g + 8) * 96 + col) = __float22bfloat162_rn(v1);
    }
}

// ---------------- layer-3 pooled agg + deferred GEMV (prescaled input) ----------------
__global__ void __launch_bounds__(256, 2) k_pool3(
        const float* __restrict__ W, const float* __restrict__ bias, int side) {
    extern __shared__ char sm_raw[];
    float (*red)[96] = (float(*)[96])sm_raw;
    float* Ws = (float*)(sm_raw + 64 * 96 * 4);
    int b = blockIdx.x, tid = threadIdx.x;
    int start = g_boffs[side][b], end = g_boffs[side][b + 1];
    size_t nbase = (size_t)side * N_;

    for (int i = tid; i < 96 * 96 / 4; i += 256)
        *(float4*)&Ws[i * 4] = *(const float4*)&W[i * 4];

    int slot = tid >> 2, l = tid & 3;
    int lane = tid & 31;
    int qb = lane & ~3;
    unsigned QM = 0xFu << qb;            // quad member mask (quad = one node slot)
    float2 psum[12];
#pragma unroll
    for (int j = 0; j < 12; ++j) psum[j] = make_float2(0.f, 0.f);

    for (int ln = start + slot; ln < end; ln += 64) {
        size_t node = nbase + ln;
        float dn = g_dinv[node];
        int r = 0;
        if (l < 2) r = g_rowptr[node + l];
        int pstart = __shfl_sync(QM, r, qb);
        int pend   = __shfl_sync(QM, r, qb + 1);
        float2 acc[12];
        const uint4* sp = (const uint4*)(g_bufB + node * 96 + l * 24);
#pragma unroll
        for (int v = 0; v < 3; ++v) {
            uint4 u = sp[v];
            const __nv_bfloat162* h = (const __nv_bfloat162*)&u;
#pragma unroll
            for (int q = 0; q < 4; ++q)
                acc[v * 4 + q] = __bfloat1622float2(h[q]);
        }
        for (int p = pstart; p < pend; p += 4) {
            int myi = p + l;
            int sl = (myi < pend) ? g_csr[myi] : -1;
            const uint4* bp[4];
            float wg[4];
#pragma unroll
            for (int j = 0; j < 4; ++j) {
                int sj = __shfl_sync(QM, sl, qb + j);
                int sjc = sj >= 0 ? sj : 0;
                bp[j] = (const uint4*)(g_bufB + (size_t)sjc * 96 + l * 24);
                wg[j] = sj >= 0 ? 1.f : 0.f;
            }
            uint4 u[4][3];
#pragma unroll
            for (int j = 0; j < 4; ++j)
#pragma unroll
                for (int v = 0; v < 3; ++v) u[j][v] = bp[j][v];
#pragma unroll
            for (int j = 0; j < 4; ++j) {
#pragma unroll
                for (int v = 0; v < 3; ++v) {
                    const __nv_bfloat162* h = (const __nv_bfloat162*)&u[j][v];
#pragma unroll
                    for (int q = 0; q < 4; ++q) {
                        float2 vv = __bfloat1622float2(h[q]);
                        acc[v * 4 + q].x += wg[j] * vv.x;
                        acc[v * 4 + q].y += wg[j] * vv.y;
                    }
                }
            }
        }
#pragma unroll
        for (int j = 0; j < 12; ++j) {
            psum[j].x += dn * acc[j].x;
            psum[j].y += dn * acc[j].y;
        }
    }
#pragma unroll
    for (int j = 0; j < 12; ++j) {
        int f = l * 24 + j * 2;
        red[slot][f] = psum[j].x;
        red[slot][f + 1] = psum[j].y;
    }
    __syncthreads();
    for (int o = 32; o > 0; o >>= 1) {
        if (slot < o) {
#pragma unroll
            for (int j = 0; j < 6; ++j) {
                float4 a = *(float4*)&red[slot][l * 24 + j * 4];
                float4 c = *(float4*)&red[slot + o][l * 24 + j * 4];
                a.x += c.x; a.y += c.y; a.z += c.z; a.w += c.w;
                *(float4*)&red[slot][l * 24 + j * 4] = a;
            }
        }
        __syncthreads();
    }

    if (tid < 96) {
        float ic = 1.f / fmaxf((float)(end - start), 1.f);
        float accv = bias[tid];
#pragma unroll 4
        for (int k = 0; k < 96; ++k) accv += red[0][k] * ic * Ws[k * 96 + tid];
        g_mean[side][(size_t)b * 96 + tid] = accv;
    }
}

// ---------------- final MLP ----------------
__global__ void k_final(const float* __restrict__ W0, const float* __restrict__ b0,
                        const float* __restrict__ W1, const float* __restrict__ b1,
                        float* __restrict__ out) {
    __shared__ float in[320];
    __shared__ float red[128];
    int b = blockIdx.x, t = threadIdx.x;
    for (int i = t; i < 96; i += 128) {
        in[i]      = g_mean[0][(size_t)b * 96 + i];
        in[96 + i] = g_mean[1][(size_t)b * 96 + i];
    }
    for (int i = t; i < 64; i += 128) {
        in[192 + i] = g_att[0][(size_t)b * 64 + i];
        in[256 + i] = g_att[1][(size_t)b * 64 + i];
    }
    __syncthreads();
    float p = 0.f;
    if (t < 96) {
        float acc = b0[t];
        for (int k = 0; k < 320; ++k) acc += in[k] * W0[(size_t)k * 96 + t];
        p = fmaxf(acc, 0.f) * W1[t];
    }
    red[t] = p;
    __syncthreads();
    for (int s = 64; s > 0; s >>= 1) {
        if (t < s) red[t] += red[t + s];
        __syncthreads();
    }
    if (t == 0) out[b] = red[0] + b1[0];
}

// ---------------- launch ----------------
static inline int TB(int n) { return (n + 255) / 256; }

extern "C" void kernel_launch(void* const* d_in, const int* in_sizes, int n_in,
                              void* d_out, int out_size) {
    const float* x_p   = (const float*)d_in[0];
    const float* x_d   = (const float*)d_in[1];
    const int*   ei_p  = (const int*)d_in[4];
    const int*   ei_d  = (const int*)d_in[5];
    const int*   bat_p = (const int*)d_in[6];
    const int*   bat_d = (const int*)d_in[7];
    const float* gW1 = (const float*)d_in[8];
    const float* gb1 = (const float*)d_in[9];
    const float* gW2 = (const float*)d_in[10];
    const float* gb2 = (const float*)d_in[11];
    const float* convW[2][3] = {
        {(const float*)d_in[12], (const float*)d_in[14], (const float*)d_in[16]},
        {(const float*)d_in[18], (const float*)d_in[20], (const float*)d_in[22]}};
    const float* convB[2][3] = {
        {(const float*)d_in[13], (const float*)d_in[15], (const float*)d_in[17]},
        {(const float*)d_in[19], (const float*)d_in[21], (const float*)d_in[23]}};
    const float* lW0 = (const float*)d_in[24];
    const float* lb0 = (const float*)d_in[25];
    const float* lW1 = (const float*)d_in[26];
    const float* lb1 = (const float*)d_in[27];
    float* out = (float*)d_out;

    __nv_bfloat16 *xh, *bufA, *bufB;
    cudaGetSymbolAddress((void**)&xh, g_xh);
    cudaGetSymbolAddress((void**)&bufA, g_bufA);
    cudaGetSymbolAddress((void**)&bufB, g_bufB);

    const int SM_L1   = (64 + 96) * (64 + 8) * 2 + 96 * 4;      // 23424
    const int SM_L2   = (64 + 96) * (96 + 8) * 2 + 96 * 4;      // 33664
    const int SM_GATE = (64 * 68 * 2 + 2 * 64) * 4;             // 35328
    const int SM_P3   = (64 * 96 + 96 * 96) * 4;                // 61440
    cudaFuncSetAttribute(k_gate,  cudaFuncAttributeMaxDynamicSharedMemorySize, SM_GATE);
    cudaFuncSetAttribute(k_pool3, cudaFuncAttributeMaxDynamicSharedMemorySize, SM_P3);

    // ---- combined CSR build first (dinv needed by gate's prescaled emission) ----
    k_csr_init<<<TB(N2_), 256>>>();
    k_count<<<TB(E2_), 256>>>(ei_p, ei_d);
    k_scan1<<<NT2_, 1024>>>();
    k_scan2<<<1, 1024>>>();
    k_scan3<<<TB(N2_), 256>>>();
    k_fill<<<TB(E2_), 256>>>(ei_p, ei_d);

    // ---- gate (+ prescaled bf16 x), batch offsets, attention pool ----
    k_gate<<<2 * (N_ / 64), 256, SM_GATE>>>(x_p, x_d, gW1, gb1, gW2, gb2);
    k_boffs<<<TB(N2_), 256>>>(bat_p, bat_d);
    k_att<<<2 * B_, 256>>>(x_p, x_d);

    // ---- per-side fused HMMA layers + pooled layer 3 ----
    for (int side = 0; side < 2; ++side) {
        k_layer<64><<<N_ / 64, 256, SM_L1>>>(xh, convW[side][0], convB[side][0], bufA, side);
        k_layer<96><<<N_ / 64, 256, SM_L2>>>(bufA, convW[side][1], convB[side][1], bufB, side);
        k_pool3<<<B_, 256, SM_P3>>>(convW[side][2], convB[side][2], side);
    }

    // ---- final MLP ----
    k_final<<<B_, 128>>>(lW0, lb0, lW1, lb1, out);
}

// round 17
// speedup vs baseline: 1.1673x; 1.1673x over previous
#include <cuda_runtime.h>
#include <cuda_bf16.h>
#include <cstddef>

// Problem constants
#define N_ 400000
#define E_ 1600000
#define B_ 8192
#define F_ 64
#define H_ 96
#define N2_ 800000                      // combined nodes (2 sides)
#define E2_ 3200000                     // combined edges
#define NT2_ ((N2_ + 1023) / 1024)      // 782 scan tiles

// ---------------- scratch (device globals; no allocations allowed) ----------------
__device__ __nv_bfloat16 g_xh [(size_t)N2_ * F_];   // dinv-prescaled bf16 x
__device__ __nv_bfloat16 g_bufA[(size_t)N2_ * H_];  // dinv-prescaled layer1 out
__device__ __nv_bfloat16 g_bufB[(size_t)N2_ * H_];  // dinv-prescaled layer2 out
__device__ float g_dinv[N2_];
__device__ int   g_deg[N2_];
__device__ int   g_rowptr[N2_ + 1];
__device__ int   g_fill[N2_];
__device__ int   g_csr[E2_];
__device__ int   g_bsum[NT2_];
__device__ float g_gate[N2_];
__device__ int   g_boffs[2][B_ + 1];
__device__ float g_att [2][B_ * F_];
__device__ float g_mean[2][B_ * H_];

// HMMA bf16: D(16x8,f32) += A(16x16,bf16 row) * B(16x8,bf16 col)
__device__ __forceinline__ void mma_bf16(float& c0, float& c1, float& c2, float& c3,
                                         unsigned a0, unsigned a1, unsigned a2, unsigned a3,
                                         unsigned b0, unsigned b1) {
    asm volatile(
        "mma.sync.aligned.m16n8k16.row.col.f32.bf16.bf16.f32 "
        "{%0,%1,%2,%3}, {%4,%5,%6,%7}, {%8,%9}, {%0,%1,%2,%3};"
        : "+f"(c0), "+f"(c1), "+f"(c2), "+f"(c3)
        : "r"(a0), "r"(a1), "r"(a2), "r"(a3), "r"(b0), "r"(b1));
}

// HMMA tf32: D(16x8,f32) += A(16x8,tf32 row) * B(8x8,tf32 col)
__device__ __forceinline__ void mma_tf32(float& c0, float& c1, float& c2, float& c3,
                                         unsigned a0, unsigned a1, unsigned a2, unsigned a3,
                                         unsigned b0, unsigned b1) {
    asm volatile(
        "mma.sync.aligned.m16n8k8.row.col.f32.tf32.tf32.f32 "
        "{%0,%1,%2,%3}, {%4,%5,%6,%7}, {%8,%9}, {%0,%1,%2,%3};"
        : "+f"(c0), "+f"(c1), "+f"(c2), "+f"(c3)
        : "r"(a0), "r"(a1), "r"(a2), "r"(a3), "r"(b0), "r"(b1));
}

__device__ __forceinline__ unsigned f2tf32(float f) {
    unsigned u;
    asm("cvt.rna.tf32.f32 %0, %1;" : "=r"(u) : "f"(f));
    return u;
}

// ---------------- gate MLP (both sides, tf32 HMMA) + prescaled bf16 x emission ----------------
__global__ void k_gate(const float* __restrict__ x_p, const float* __restrict__ x_d,
                       const float* __restrict__ W1, const float* __restrict__ b1,
                       const float* __restrict__ W2, const float* __restrict__ b2) {
    extern __shared__ char sm_raw[];
    float* xs  = (float*)sm_raw;                       // [64][68] row-major
    float* W1T = xs + 64 * 68;                          // [64n][68k]
    float* b1s = W1T + 64 * 68;
    float* W2s = b1s + 64;
    __shared__ float gred[64][2];
    int tid = threadIdx.x;
    int side = blockIdx.x >= (N_ / 64);
    int lrow0 = (blockIdx.x - side * (N_ / 64)) * 64;
    const float* x = side ? x_d : x_p;
    size_t gbase = (size_t)side * N_;

    for (int i = tid; i < 64 * 64; i += 256) {
        int k = i >> 6, n = i & 63;
        W1T[n * 68 + k] = W1[i];
    }
    if (tid < 64) { b1s[tid] = b1[tid]; W2s[tid] = W2[tid]; }

    // stage x rows (unscaled, for GEMM) + emit dinv-prescaled bf16 copy
    {
        int g = tid >> 2, l = tid & 3;
        float dn = g_dinv[gbase + lrow0 + g];
        const float4* sp = (const float4*)(x + (size_t)(lrow0 + g) * 64) + l * 4;
        __nv_bfloat162 hv[8];
#pragma unroll
        for (int j = 0; j < 4; ++j) {
            float4 v = sp[j];
            *(float4*)&xs[g * 68 + l * 16 + j * 4] = v;
            hv[2 * j]     = __float22bfloat162_rn(make_float2(v.x * dn, v.y * dn));
            hv[2 * j + 1] = __float22bfloat162_rn(make_float2(v.z * dn, v.w * dn));
        }
        *(uint4*)(g_xh + (gbase + lrow0 + g) * 64 + l * 16)     = *(uint4*)&hv[0];
        *(uint4*)(g_xh + (gbase + lrow0 + g) * 64 + l * 16 + 8) = *(uint4*)&hv[4];
    }
    __syncthreads();

    int lane = tid & 31, w = tid >> 5;
    int g = lane >> 2, tig = lane & 3;
    int rw = (w >> 1) * 16, cw = (w & 1) * 32;
    float hacc[4][4];
#pragma unroll
    for (int nt = 0; nt < 4; ++nt)
#pragma unroll
        for (int q = 0; q < 4; ++q) hacc[nt][q] = 0.f;

#pragma unroll
    for (int k0 = 0; k0 < 64; k0 += 8) {
        unsigned a0 = f2tf32(xs[(rw + g) * 68 + k0 + tig]);
        unsigned a1 = f2tf32(xs[(rw + g + 8) * 68 + k0 + tig]);
        unsigned a2 = f2tf32(xs[(rw + g) * 68 + k0 + tig + 4]);
        unsigned a3 = f2tf32(xs[(rw + g + 8) * 68 + k0 + tig + 4]);
#pragma unroll
        for (int nt = 0; nt < 4; ++nt) {
            int n = cw + nt * 8 + g;
            unsigned b0 = f2tf32(W1T[n * 68 + k0 + tig]);
            unsigned b1r = f2tf32(W1T[n * 68 + k0 + tig + 4]);
            mma_tf32(hacc[nt][0], hacc[nt][1], hacc[nt][2], hacc[nt][3],
                     a0, a1, a2, a3, b0, b1r);
        }
    }

    float p0 = 0.f, p1 = 0.f;
#pragma unroll
    for (int nt = 0; nt < 4; ++nt) {
        int col = cw + nt * 8 + tig * 2;
        float ba = b1s[col], bb = b1s[col + 1];
        float wa = W2s[col], wb = W2s[col + 1];
        p0 += fmaxf(hacc[nt][0] + ba, 0.f) * wa + fmaxf(hacc[nt][1] + bb, 0.f) * wb;
        p1 += fmaxf(hacc[nt][2] + ba, 0.f) * wa + fmaxf(hacc[nt][3] + bb, 0.f) * wb;
    }
    p0 += __shfl_xor_sync(0xffffffffu, p0, 1);
    p0 += __shfl_xor_sync(0xffffffffu, p0, 2);
    p1 += __shfl_xor_sync(0xffffffffu, p1, 1);
    p1 += __shfl_xor_sync(0xffffffffu, p1, 2);
    if (tig == 0) {
        gred[rw + g][w & 1] = p0;
        gred[rw + g + 8][w & 1] = p1;
    }
    __syncthreads();
    if (tid < 64)
        g_gate[gbase + lrow0 + tid] = gred[tid][0] + gred[tid][1] + b2[0];
}

// ---------------- batch segment offsets ----------------
__global__ void k_boffs(const int* __restrict__ bat_p, const int* __restrict__ bat_d) {
    int gi = blockIdx.x * blockDim.x + threadIdx.x;
    if (gi >= N2_) return;
    int side = gi >= N_;
    int i = gi - side * N_;
    const int* batch = side ? bat_d : bat_p;
    int b = batch[i];
    if (i == 0) {
        for (int bb = 0; bb <= b; ++bb) g_boffs[side][bb] = 0;
    } else {
        int pb = batch[i - 1];
        for (int bb = pb + 1; bb <= b; ++bb) g_boffs[side][bb] = i;
    }
    if (i == N_ - 1) {
        for (int bb = b + 1; bb <= B_; ++bb) g_boffs[side][bb] = N_;
    }
}

// ---------------- attention pool ----------------
__global__ void k_att(const float* __restrict__ x_p, const float* __restrict__ x_d) {
    __shared__ float sred[256];
    __shared__ float red[64][64];
    int side = blockIdx.x >> 13;
    int b = blockIdx.x & (B_ - 1);
    int tid = threadIdx.x;
    const float* x = side ? x_d : x_p;
    const float* gate = g_gate + (size_t)side * N_;
    int start = g_boffs[side][b], end = g_boffs[side][b + 1];

    float m = -1e30f;
    for (int i = start + tid; i < end; i += 256) m = fmaxf(m, gate[i]);
    sred[tid] = m;
    __syncthreads();
    for (int o = 128; o > 0; o >>= 1) {
        if (tid < o) sred[tid] = fmaxf(sred[tid], sred[tid + o]);
        __syncthreads();
    }
    float gmax = sred[0];
    __syncthreads();

    float s = 0.f;
    for (int i = start + tid; i < end; i += 256) s += expf(gate[i] - gmax);
    sred[tid] = s;
    __syncthreads();
    for (int o = 128; o > 0; o >>= 1) {
        if (tid < o) sred[tid] += sred[tid + o];
        __syncthreads();
    }
    float denom = sred[0];

    int slot = tid >> 2, l = tid & 3;
    float4 acc[4];
#pragma unroll
    for (int j = 0; j < 4; ++j) acc[j] = make_float4(0.f, 0.f, 0.f, 0.f);
    for (int i = start + slot; i < end; i += 64) {
        float e = expf(gate[i] - gmax);
        const float4* xp = (const float4*)(x + (size_t)i * 64) + l * 4;
#pragma unroll
        for (int j = 0; j < 4; ++j) {
            float4 v = xp[j];
            acc[j].x += e * v.x; acc[j].y += e * v.y;
            acc[j].z += e * v.z; acc[j].w += e * v.w;
        }
    }
#pragma unroll
    for (int j = 0; j < 4; ++j) *(float4*)&red[slot][l * 16 + j * 4] = acc[j];
    __syncthreads();
    for (int o = 32; o > 0; o >>= 1) {
        if (slot < o) {
#pragma unroll
            for (int j = 0; j < 4; ++j) {
                float4 a = *(float4*)&red[slot][l * 16 + j * 4];
                float4 c = *(float4*)&red[slot + o][l * 16 + j * 4];
                a.x += c.x; a.y += c.y; a.z += c.z; a.w += c.w;
                *(float4*)&red[slot][l * 16 + j * 4] = a;
            }
        }
        __syncthreads();
    }
    if (slot == 0) {
        float inv = (end > start) ? 1.f / denom : 0.f;
#pragma unroll
        for (int j = 0; j < 16; ++j)
            g_att[side][(size_t)b * 64 + l * 16 + j] = red[0][l * 16 + j] * inv;
    }
}

// ---------------- combined CSR build ----------------
__global__ void k_csr_init() {
    int i = blockIdx.x * blockDim.x + threadIdx.x;
    if (i < N2_) { g_deg[i] = 0; g_fill[i] = 0; }
}
__global__ void k_count(const int* __restrict__ ei_p, const int* __restrict__ ei_d) {
    int e = blockIdx.x * blockDim.x + threadIdx.x;
    if (e >= E2_) return;
    int side = e >= E_;
    int idx = e - side * E_;
    const int* ei = side ? ei_d : ei_p;
    atomicAdd(&g_deg[ei[E_ + idx] + side * N_], 1);
}
__global__ void k_scan1() {
    __shared__ int s[1024];
    int tx = threadIdx.x;
    int i = blockIdx.x * 1024 + tx;
    int v = (i < N2_) ? g_deg[i] : 0;
    s[tx] = v;
    __syncthreads();
    for (int o = 1; o < 1024; o <<= 1) {
        int t = (tx >= o) ? s[tx - o] : 0;
        __syncthreads();
        s[tx] += t;
        __syncthreads();
    }
    if (i < N2_) g_rowptr[i] = s[tx] - v;
    if (tx == 1023) g_bsum[blockIdx.x] = s[1023];
}
__global__ void k_scan2() {
    __shared__ int s[1024];
    int tx = threadIdx.x;
    int v = (tx < NT2_) ? g_bsum[tx] : 0;
    s[tx] = v;
    __syncthreads();
    for (int o = 1; o < 1024; o <<= 1) {
        int t = (tx >= o) ? s[tx - o] : 0;
        __syncthreads();
        s[tx] += t;
        __syncthreads();
    }
    if (tx < NT2_) g_bsum[tx] = s[tx] - v;
}
__global__ void k_scan3() {     // + fused dinv
    int i = blockIdx.x * blockDim.x + threadIdx.x;
    if (i < N2_) {
        g_rowptr[i] += g_bsum[i >> 10];
        g_dinv[i] = rsqrtf((float)(g_deg[i] + 1));
    }
    if (i == 0) g_rowptr[N2_] = E2_;
}
__global__ void k_fill(const int* __restrict__ ei_p, const int* __restrict__ ei_d) {
    int e = blockIdx.x * blockDim.x + threadIdx.x;
    if (e >= E2_) return;
    int side = e >= E_;
    int idx = e - side * E_;
    const int* ei = side ? ei_d : ei_p;
    int d = ei[E_ + idx] + side * N_;
    int pos = g_rowptr[d] + atomicAdd(&g_fill[d], 1);
    g_csr[pos] = ei[idx] + side * N_;
}

// ---------------- fused layer (HMMA): out' = dinv * relu(agg(in') @ W + b) ----------------
// in'/out' are dinv-prescaled: agg_d = dinv_d * (in'_d + sum_nbr in'_s).
// block = 64 dst rows, 256 threads; simple per-lane index loads (L1-hit broadcast),
// unroll-by-2 neighbor prefetch (R8 structure — fastest measured).
template <int FIN>
__global__ void k_layer(const __nv_bfloat16* __restrict__ in, const float* __restrict__ W,
                        const float* __restrict__ bias, __nv_bfloat16* __restrict__ out,
                        int side) {
    constexpr int AP = FIN + 8;
    constexpr int CH = FIN / 4;          // features per lane
    constexpr int NV = CH / 8;           // uint4 per lane per row (2 or 3)
    extern __shared__ char sm_raw[];
    __nv_bfloat16* As = (__nv_bfloat16*)sm_raw;
    __nv_bfloat16* Wt = As + 64 * AP;
    float* bs = (float*)(sm_raw + (64 + 96) * AP * 2);
    int tid = threadIdx.x;
    size_t row0 = (size_t)side * N_ + blockIdx.x * 64;

    for (int i = tid; i < FIN * 96; i += 256) {
        int k = i / 96, n = i % 96;
        Wt[n * AP + k] = __float2bfloat16(W[i]);
    }
    if (tid < 96) bs[tid] = bias[tid];

    // ---- gather phase (prescaled input: inner loop is pure accumulate) ----
    {
        int g = tid >> 2, l = tid & 3;
        size_t node = row0 + g;
        float dn = g_dinv[node];
        float2 acc[CH / 2];
        const uint4* sp = (const uint4*)(in + node * FIN + l * CH);
#pragma unroll
        for (int v = 0; v < NV; ++v) {
            uint4 u = sp[v];
            const __nv_bfloat162* h = (const __nv_bfloat162*)&u;
#pragma unroll
            for (int q = 0; q < 4; ++q)
                acc[v * 4 + q] = __bfloat1622float2(h[q]);
        }
        int p = g_rowptr[node], p1 = g_rowptr[node + 1];
        for (; p + 2 <= p1; p += 2) {
            int s0 = g_csr[p], s1 = g_csr[p + 1];
            const uint4* np0 = (const uint4*)(in + (size_t)s0 * FIN + l * CH);
            const uint4* np1 = (const uint4*)(in + (size_t)s1 * FIN + l * CH);
            uint4 u0[NV], u1[NV];
#pragma unroll
            for (int v = 0; v < NV; ++v) { u0[v] = np0[v]; u1[v] = np1[v]; }
#pragma unroll
            for (int v = 0; v < NV; ++v) {
                const __nv_bfloat162* h0 = (const __nv_bfloat162*)&u0[v];
                const __nv_bfloat162* h1 = (const __nv_bfloat162*)&u1[v];
#pragma unroll
                for (int q = 0; q < 4; ++q) {
                    float2 v0 = __bfloat1622float2(h0[q]);
                    float2 v1 = __bfloat1622float2(h1[q]);
                    acc[v * 4 + q].x += v0.x + v1.x;
                    acc[v * 4 + q].y += v0.y + v1.y;
                }
            }
        }
        if (p < p1) {
            int s = g_csr[p];
            const uint4* np = (const uint4*)(in + (size_t)s * FIN + l * CH);
#pragma unroll
            for (int v = 0; v < NV; ++v) {
                uint4 u = np[v];
                const __nv_bfloat162* h = (const __nv_bfloat162*)&u;
#pragma unroll
                for (int q = 0; q < 4; ++q) {
                    float2 vv = __bfloat1622float2(h[q]);
                    acc[v * 4 + q].x += vv.x;
                    acc[v * 4 + q].y += vv.y;
                }
            }
        }
#pragma unroll
        for (int j2 = 0; j2 < CH / 2; ++j2) {
            float2 a = acc[j2];
            a.x *= dn; a.y *= dn;
            *(__nv_bfloat162*)(As + g * AP + l * CH + 2 * j2) = __float22bfloat162_rn(a);
        }
    }
    __syncthreads();

    // ---- HMMA phase: [64 x FIN] @ [FIN x 96] ----
    int lane = tid & 31, w = tid >> 5;
    int g = lane >> 2, tig = lane & 3;
    int rw = (w >> 1) * 16, cw = (w & 1) * 48;
    float acc[6][4];
#pragma unroll
    for (int nt = 0; nt < 6; ++nt)
#pragma unroll
        for (int q = 0; q < 4; ++q) acc[nt][q] = 0.f;

#pragma unroll
    for (int k0 = 0; k0 < FIN; k0 += 16) {
        unsigned a0 = *(const unsigned*)(As + (rw + g) * AP + k0 + 2 * tig);
        unsigned a1 = *(const unsigned*)(As + (rw + g + 8) * AP + k0 + 2 * tig);
        unsigned a2 = *(const unsigned*)(As + (rw + g) * AP + k0 + 2 * tig + 8);
        unsigned a3 = *(const unsigned*)(As + (rw + g + 8) * AP + k0 + 2 * tig + 8);
#pragma unroll
        for (int nt = 0; nt < 6; ++nt) {
            int n = cw + nt * 8 + g;
            unsigned b0 = *(const unsigned*)(Wt + n * AP + k0 + 2 * tig);
            unsigned b1 = *(const unsigned*)(Wt + n * AP + k0 + 2 * tig + 8);
            mma_bf16(acc[nt][0], acc[nt][1], acc[nt][2], acc[nt][3],
                     a0, a1, a2, a3, b0, b1);
        }
    }

    // ---- epilogue: bias + relu + prescale by dinv(out row) + bf16 store ----
    float d0 = g_dinv[row0 + rw + g];
    float d1 = g_dinv[row0 + rw + g + 8];
#pragma unroll
    for (int nt = 0; nt < 6; ++nt) {
        int col = cw + nt * 8 + tig * 2;
        float bx = bs[col], by = bs[col + 1];
        float2 v0 = make_float2(fmaxf(acc[nt][0] + bx, 0.f) * d0,
                                fmaxf(acc[nt][1] + by, 0.f) * d0);
        float2 v1 = make_float2(fmaxf(acc[nt][2] + bx, 0.f) * d1,
                                fmaxf(acc[nt][3] + by, 0.f) * d1);
        *(__nv_bfloat162*)(out + (row0 + rw + g) * 96 + col)     = __float22bfloat162_rn(v0);
        *(__nv_bfloat162*)(out + (row0 + rw + g + 8) * 96 + col) = __float22bfloat162_rn(v1);
    }
}

// ---------------- layer-3 pooled agg + deferred GEMV (prescaled input) ----------------
__global__ void k_pool3(const float* __restrict__ W, const float* __restrict__ bias,
                        int side) {
    extern __shared__ char sm_raw[];
    float (*red)[96] = (float(*)[96])sm_raw;
    float* Ws = (float*)(sm_raw + 64 * 96 * 4);
    int b = blockIdx.x, tid = threadIdx.x;
    int start = g_boffs[side][b], end = g_boffs[side][b + 1];
    size_t nbase = (size_t)side * N_;

    for (int i = tid; i < 96 * 96 / 4; i += 256)
        *(float4*)&Ws[i * 4] = *(const float4*)&W[i * 4];

    int slot = tid >> 2, l = tid & 3;
    float2 psum[12];
#pragma unroll
    for (int j = 0; j < 12; ++j) psum[j] = make_float2(0.f, 0.f);

    for (int ln = start + slot; ln < end; ln += 64) {
        size_t node = nbase + ln;
        float dn = g_dinv[node];
        float2 acc[12];
        const uint4* sp = (const uint4*)(g_bufB + node * 96 + l * 24);
#pragma unroll
        for (int v = 0; v < 3; ++v) {
            uint4 u = sp[v];
            const __nv_bfloat162* h = (const __nv_bfloat162*)&u;
#pragma unroll
            for (int q = 0; q < 4; ++q)
                acc[v * 4 + q] = __bfloat1622float2(h[q]);
        }
        int p = g_rowptr[node], p1 = g_rowptr[node + 1];
        for (; p + 2 <= p1; p += 2) {
            int s0 = g_csr[p], s1 = g_csr[p + 1];
            const uint4* np0 = (const uint4*)(g_bufB + (size_t)s0 * 96 + l * 24);
            const uint4* np1 = (const uint4*)(g_bufB + (size_t)s1 * 96 + l * 24);
            uint4 u0[3], u1[3];
#pragma unroll
            for (int v = 0; v < 3; ++v) { u0[v] = np0[v]; u1[v] = np1[v]; }
#pragma unroll
            for (int v = 0; v < 3; ++v) {
                const __nv_bfloat162* h0 = (const __nv_bfloat162*)&u0[v];
                const __nv_bfloat162* h1 = (const __nv_bfloat162*)&u1[v];
#pragma unroll
                for (int q = 0; q < 4; ++q) {
                    float2 v0 = __bfloat1622float2(h0[q]);
                    float2 v1 = __bfloat1622float2(h1[q]);
                    acc[v * 4 + q].x += v0.x + v1.x;
                    acc[v * 4 + q].y += v0.y + v1.y;
                }
            }
        }
        if (p < p1) {
            int s = g_csr[p];
            const uint4* np = (const uint4*)(g_bufB + (size_t)s * 96 + l * 24);
#pragma unroll
            for (int v = 0; v < 3; ++v) {
                uint4 u = np[v];
                const __nv_bfloat162* h = (const __nv_bfloat162*)&u;
#pragma unroll
                for (int q = 0; q < 4; ++q) {
                    float2 vv = __bfloat1622float2(h[q]);
                    acc[v * 4 + q].x += vv.x;
                    acc[v * 4 + q].y += vv.y;
                }
            }
        }
#pragma unroll
        for (int j = 0; j < 12; ++j) {
            psum[j].x += dn * acc[j].x;
            psum[j].y += dn * acc[j].y;
        }
    }
#pragma unroll
    for (int j = 0; j < 12; ++j) {
        int f = l * 24 + j * 2;
        red[slot][f] = psum[j].x;
        red[slot][f + 1] = psum[j].y;
    }
    __syncthreads();
    for (int o = 32; o > 0; o >>= 1) {
        if (slot < o) {
#pragma unroll
            for (int j = 0; j < 6; ++j) {
                float4 a = *(float4*)&red[slot][l * 24 + j * 4];
                float4 c = *(float4*)&red[slot + o][l * 24 + j * 4];
                a.x += c.x; a.y += c.y; a.z += c.z; a.w += c.w;
                *(float4*)&red[slot][l * 24 + j * 4] = a;
            }
        }
        __syncthreads();
    }

    if (tid < 96) {
        float ic = 1.f / fmaxf((float)(end - start), 1.f);
        float accv = bias[tid];
#pragma unroll 4
        for (int k = 0; k < 96; ++k) accv += red[0][k] * ic * Ws[k * 96 + tid];
        g_mean[side][(size_t)b * 96 + tid] = accv;
    }
}

// ---------------- final MLP ----------------
__global__ void k_final(const float* __restrict__ W0, const float* __restrict__ b0,
                        const float* __restrict__ W1, const float* __restrict__ b1,
                        float* __restrict__ out) {
    __shared__ float in[320];
    __shared__ float red[128];
    int b = blockIdx.x, t = threadIdx.x;
    for (int i = t; i < 96; i += 128) {
        in[i]      = g_mean[0][(size_t)b * 96 + i];
        in[96 + i] = g_mean[1][(size_t)b * 96 + i];
    }
    for (int i = t; i < 64; i += 128) {
        in[192 + i] = g_att[0][(size_t)b * 64 + i];
        in[256 + i] = g_att[1][(size_t)b * 64 + i];
    }
    __syncthreads();
    float p = 0.f;
    if (t < 96) {
        float acc = b0[t];
        for (int k = 0; k < 320; ++k) acc += in[k] * W0[(size_t)k * 96 + t];
        p = fmaxf(acc, 0.f) * W1[t];
    }
    red[t] = p;
    __syncthreads();
    for (int s = 64; s > 0; s >>= 1) {
        if (t < s) red[t] += red[t + s];
        __syncthreads();
    }
    if (t == 0) out[b] = red[0] + b1[0];
}

// ---------------- launch ----------------
static inline int TB(int n) { return (n + 255) / 256; }

extern "C" void kernel_launch(void* const* d_in, const int* in_sizes, int n_in,
                              void* d_out, int out_size) {
    const float* x_p   = (const float*)d_in[0];
    const float* x_d   = (const float*)d_in[1];
    const int*   ei_p  = (const int*)d_in[4];
    const int*   ei_d  = (const int*)d_in[5];
    const int*   bat_p = (const int*)d_in[6];
    const int*   bat_d = (const int*)d_in[7];
    const float* gW1 = (const float*)d_in[8];
    const float* gb1 = (const float*)d_in[9];
    const float* gW2 = (const float*)d_in[10];
    const float* gb2 = (const float*)d_in[11];
    const float* convW[2][3] = {
        {(const float*)d_in[12], (const float*)d_in[14], (const float*)d_in[16]},
        {(const float*)d_in[18], (const float*)d_in[20], (const float*)d_in[22]}};
    const float* convB[2][3] = {
        {(const float*)d_in[13], (const float*)d_in[15], (const float*)d_in[17]},
        {(const float*)d_in[19], (const float*)d_in[21], (const float*)d_in[23]}};
    const float* lW0 = (const float*)d_in[24];
    const float* lb0 = (const float*)d_in[25];
    const float* lW1 = (const float*)d_in[26];
    const float* lb1 = (const float*)d_in[27];
    float* out = (float*)d_out;

    __nv_bfloat16 *xh, *bufA, *bufB;
    cudaGetSymbolAddress((void**)&xh, g_xh);
    cudaGetSymbolAddress((void**)&bufA, g_bufA);
    cudaGetSymbolAddress((void**)&bufB, g_bufB);

    const int SM_L1   = (64 + 96) * (64 + 8) * 2 + 96 * 4;      // 23424
    const int SM_L2   = (64 + 96) * (96 + 8) * 2 + 96 * 4;      // 33664
    const int SM_GATE = (64 * 68 * 2 + 2 * 64) * 4;             // 35328
    const int SM_P3   = (64 * 96 + 96 * 96) * 4;                // 61440
    cudaFuncSetAttribute(k_gate,  cudaFuncAttributeMaxDynamicSharedMemorySize, SM_GATE);
    cudaFuncSetAttribute(k_pool3, cudaFuncAttributeMaxDynamicSharedMemorySize, SM_P3);

    // ---- combined CSR build first (dinv needed by gate's prescaled emission) ----
    k_csr_init<<<TB(N2_), 256>>>();
    k_count<<<TB(E2_), 256>>>(ei_p, ei_d);
    k_scan1<<<NT2_, 1024>>>();
    k_scan2<<<1, 1024>>>();
    k_scan3<<<TB(N2_), 256>>>();
    k_fill<<<TB(E2_), 256>>>(ei_p, ei_d);

    // ---- gate (+ prescaled bf16 x), batch offsets, attention pool ----
    k_gate<<<2 * (N_ / 64), 256, SM_GATE>>>(x_p, x_d, gW1, gb1, gW2, gb2);
    k_boffs<<<TB(N2_), 256>>>(bat_p, bat_d);
    k_att<<<2 * B_, 256>>>(x_p, x_d);

    // ---- per-side fused HMMA layers + pooled layer 3 ----
    for (int side = 0; side < 2; ++side) {
        k_layer<64><<<N_ / 64, 256, SM_L1>>>(xh, convW[side][0], convB[side][0], bufA, side);
        k_layer<96><<<N_ / 64, 256, SM_L2>>>(bufA, convW[side][1], convB[side][1], bufB, side);
        k_pool3<<<B_, 256, SM_P3>>>(convW[side][2], convB[side][2], side);
    }

    // ---- final MLP ----
    k_final<<<B_, 128>>>(lW0, lb0, lW1, lb1, out);
}